// round 1
// baseline (speedup 1.0000x reference)
#include <cuda_runtime.h>
#include <math_constants.h>

// ---------------------------------------------------------------------------
// AttentionHead: B=8, S=2048, H=1024, D=64
//   q = x@Wq + bq ; k = x@Wk + bk ; v = x@Wv + bv        (GEMM 16384x1024x192)
//   out = softmax(q k^T / sqrt(64), mask) @ v            (flash-style)
// fp32 throughout. Round 1 baseline: fp32 FMA-pipe bound.
// ---------------------------------------------------------------------------

#define BATCH 8
#define SEQ   2048
#define HID   1024
#define DHEAD 64
#define ROWS_TOTAL (BATCH * SEQ)   // 16384

// Scratch for projections (no cudaMalloc allowed)
__device__ float g_q[ROWS_TOTAL * DHEAD];
__device__ float g_k[ROWS_TOTAL * DHEAD];
__device__ float g_v[ROWS_TOTAL * DHEAD];

// ---------------------------------------------------------------------------
// Kernel 1: fused QKV projection.
//   C[16384, 192] = x[16384, 1024] @ [Wq|Wk|Wv][1024, 192] + [bq|bk|bv]
//   Block tile: 64 rows x 192 cols, Kc = 16, 256 threads (16x16),
//   per-thread micro-tile 4 rows x 12 cols (48 accumulators).
// ---------------------------------------------------------------------------
__global__ __launch_bounds__(256) void proj_kernel(
    const float* __restrict__ x,
    const float* __restrict__ Wq, const float* __restrict__ bq,
    const float* __restrict__ Wk, const float* __restrict__ bk,
    const float* __restrict__ Wv, const float* __restrict__ bv)
{
    constexpr int BM = 64;
    constexpr int KC = 16;
    constexpr int NT = 192;

    __shared__ __align__(16) float xs[KC][68];   // [kk][row], pad 64->68 (16B-aligned rows)
    __shared__ __align__(16) float ws[KC][NT];   // [kk][col]

    const int tid = threadIdx.x;
    const int ty  = tid >> 4;   // 0..15 -> row group (4 rows each)
    const int tx  = tid & 15;   // 0..15 -> col group (12 cols each)
    const int rowBase = blockIdx.x * BM;

    float acc[4][12];
#pragma unroll
    for (int i = 0; i < 4; i++)
#pragma unroll
        for (int j = 0; j < 12; j++) acc[i][j] = 0.f;

    for (int k0 = 0; k0 < HID; k0 += KC) {
        __syncthreads();
        // --- load x tile: 64 rows x 16 k -> xs[kk][row] (transposed store) ---
        {
            int row = tid >> 2;           // 0..63
            int cs  = (tid & 3) * 4;      // 0,4,8,12
            float4 xv = *(const float4*)(x + (size_t)(rowBase + row) * HID + k0 + cs);
            xs[cs + 0][row] = xv.x;
            xs[cs + 1][row] = xv.y;
            xs[cs + 2][row] = xv.z;
            xs[cs + 3][row] = xv.w;
        }
        // --- load W tile: 16 k x 192 cols (cols 0-63 Wq, 64-127 Wk, 128-191 Wv)
#pragma unroll
        for (int r = 0; r < 3; r++) {
            int p   = tid + 256 * r;      // 0..767 float4 slots
            int kk  = p / 48;             // 0..15
            int col = (p % 48) * 4;       // 0..188, never straddles a matrix
            const float* src; int cc;
            if (col < 64)       { src = Wq; cc = col; }
            else if (col < 128) { src = Wk; cc = col - 64; }
            else                { src = Wv; cc = col - 128; }
            float4 wv = *(const float4*)(src + (size_t)(k0 + kk) * DHEAD + cc);
            *(float4*)&ws[kk][col] = wv;
        }
        __syncthreads();

        // --- 16 x (4x12) FMA micro-kernel ---
#pragma unroll
        for (int kk = 0; kk < KC; kk++) {
            float4 a  = *(const float4*)&xs[kk][ty * 4];
            float4 b0 = *(const float4*)&ws[kk][tx * 12 + 0];
            float4 b1 = *(const float4*)&ws[kk][tx * 12 + 4];
            float4 b2 = *(const float4*)&ws[kk][tx * 12 + 8];
            float av[4]  = {a.x, a.y, a.z, a.w};
            float bv2[12] = {b0.x, b0.y, b0.z, b0.w,
                             b1.x, b1.y, b1.z, b1.w,
                             b2.x, b2.y, b2.z, b2.w};
#pragma unroll
            for (int i = 0; i < 4; i++)
#pragma unroll
                for (int j = 0; j < 12; j++)
                    acc[i][j] += av[i] * bv2[j];
        }
    }

    // --- epilogue: add bias, route to g_q / g_k / g_v ---
    float bias[12];
#pragma unroll
    for (int j = 0; j < 12; j++) {
        int col = tx * 12 + j;
        if (col < 64)       bias[j] = bq[col];
        else if (col < 128) bias[j] = bk[col - 64];
        else                bias[j] = bv[col - 128];
    }
#pragma unroll
    for (int i = 0; i < 4; i++) {
        int row = rowBase + ty * 4 + i;
#pragma unroll
        for (int j = 0; j < 12; j++) {
            int col = tx * 12 + j;
            float val = acc[i][j] + bias[j];
            float* dst = (col < 64) ? g_q : (col < 128) ? g_k : g_v;
            dst[(size_t)row * DHEAD + (col & 63)] = val;
        }
    }
}

// ---------------------------------------------------------------------------
// Kernel 2: flash attention, one thread per query.
//   Block = 64 threads = 64 queries. Grid = (SEQ/64, BATCH) = (32, 8).
//   Per-thread state in registers: q[64], o[64], s[32], m, l.
//   Key tiles of 32 (K + V + mask) staged in smem; LDS.128 reads are
//   warp-uniform (broadcast, conflict-free).
// ---------------------------------------------------------------------------
__global__ __launch_bounds__(64) void attn_kernel(
    const int* __restrict__ mask, float* __restrict__ out)
{
    constexpr int TK = 32;
    __shared__ __align__(16) float Ks[TK][DHEAD];
    __shared__ __align__(16) float Vs[TK][DHEAD];
    __shared__ int msk[TK];

    const int b  = blockIdx.y;
    const int qi = blockIdx.x * 64 + threadIdx.x;
    const size_t qrow = ((size_t)b * SEQ + qi) * DHEAD;

    float q[DHEAD], o[DHEAD];
#pragma unroll
    for (int d = 0; d < DHEAD; d += 4) {
        float4 t = *(const float4*)(g_q + qrow + d);
        q[d] = t.x; q[d+1] = t.y; q[d+2] = t.z; q[d+3] = t.w;
        o[d] = 0.f; o[d+1] = 0.f; o[d+2] = 0.f; o[d+3] = 0.f;
    }

    float m = -CUDART_INF_F;
    float l = 0.f;
    const float* Kbase = g_k + (size_t)b * SEQ * DHEAD;
    const float* Vbase = g_v + (size_t)b * SEQ * DHEAD;
    const int*   Mbase = mask + (size_t)b * SEQ;

    for (int kt = 0; kt < SEQ; kt += TK) {
        __syncthreads();
        // stage K/V tile: 2 x 512 float4 with 64 threads -> 8 f4 each per array
#pragma unroll
        for (int p = (int)threadIdx.x; p < TK * DHEAD / 4; p += 64) {
            int j = p >> 4;
            int c = (p & 15) * 4;
            *(float4*)&Ks[j][c] = *(const float4*)(Kbase + (size_t)(kt + j) * DHEAD + c);
            *(float4*)&Vs[j][c] = *(const float4*)(Vbase + (size_t)(kt + j) * DHEAD + c);
        }
        if (threadIdx.x < TK) msk[threadIdx.x] = Mbase[kt + threadIdx.x];
        __syncthreads();

        // --- scores for this tile ---
        float s[TK];
#pragma unroll
        for (int j = 0; j < TK; j++) {
            float a0 = 0.f, a1 = 0.f;
#pragma unroll
            for (int d = 0; d < DHEAD; d += 8) {
                float4 k0 = *(const float4*)&Ks[j][d];
                float4 k1 = *(const float4*)&Ks[j][d + 4];
                a0 += q[d]   * k0.x; a0 += q[d+1] * k0.y;
                a0 += q[d+2] * k0.z; a0 += q[d+3] * k0.w;
                a1 += q[d+4] * k1.x; a1 += q[d+5] * k1.y;
                a1 += q[d+6] * k1.z; a1 += q[d+7] * k1.w;
            }
            s[j] = msk[j] ? (a0 + a1) * 0.125f : -CUDART_INF_F;
        }

        // --- online softmax update ---
        float mt = s[0];
#pragma unroll
        for (int j = 1; j < TK; j++) mt = fmaxf(mt, s[j]);
        float mnew = fmaxf(m, mt);
        if (mnew == -CUDART_INF_F) continue;   // whole tile masked (uniform across block)

        float alpha = __expf(m - mnew);        // m == -inf -> 0
        l *= alpha;
#pragma unroll
        for (int d = 0; d < DHEAD; d++) o[d] *= alpha;

#pragma unroll
        for (int j = 0; j < TK; j++) {
            float p = __expf(s[j] - mnew);     // s == -inf -> 0
            l += p;
#pragma unroll
            for (int d = 0; d < DHEAD; d += 4) {
                float4 vv = *(const float4*)&Vs[j][d];
                o[d]   += p * vv.x;
                o[d+1] += p * vv.y;
                o[d+2] += p * vv.z;
                o[d+3] += p * vv.w;
            }
        }
        m = mnew;
    }

    float inv = 1.f / l;
    float* dst = out + qrow;
#pragma unroll
    for (int d = 0; d < DHEAD; d += 4) {
        float4 r;
        r.x = o[d]   * inv;
        r.y = o[d+1] * inv;
        r.z = o[d+2] * inv;
        r.w = o[d+3] * inv;
        *(float4*)(dst + d) = r;
    }
}

// ---------------------------------------------------------------------------
extern "C" void kernel_launch(void* const* d_in, const int* in_sizes, int n_in,
                              void* d_out, int out_size)
{
    const float* x    = (const float*)d_in[0];
    const int*   mask = (const int*)  d_in[1];
    const float* Wq   = (const float*)d_in[2];
    const float* bq   = (const float*)d_in[3];
    const float* Wk   = (const float*)d_in[4];
    const float* bk   = (const float*)d_in[5];
    const float* Wv   = (const float*)d_in[6];
    const float* bv   = (const float*)d_in[7];
    float* out = (float*)d_out;

    proj_kernel<<<ROWS_TOTAL / 64, 256>>>(x, Wq, bq, Wk, bk, Wv, bv);
    attn_kernel<<<dim3(SEQ / 64, BATCH), 64>>>(mask, out);
}

// round 5
// speedup vs baseline: 1.5986x; 1.5986x over previous
#include <cuda_runtime.h>
#include <math_constants.h>
#include <cstdint>

// ---------------------------------------------------------------------------
// AttentionHead: B=8, S=2048, H=1024, D=64
//   q = x@Wq + bq ; k = x@Wk + bk ; v = x@Wv + bv        (GEMM 16384x1024x192)
//   out = softmax(q k^T / sqrt(64), mask) @ v            (flash-style)
// Round 5 (re-run of unbenched register-tiled candidate):
//   attention micro-tiles 4q x 4k (QK) / 4q x 8d (AV),
//   cp.async double-buffered K/V, Q/K stored transposed by proj.
// ---------------------------------------------------------------------------

#define BATCH 8
#define SEQ   2048
#define HID   1024
#define DHEAD 64
#define ROWS_TOTAL (BATCH * SEQ)   // 16384
#define TK 32                      // key tile
#define NTILES (SEQ / TK)          // 64
#define QB 64                      // queries per block

// Scratch (no cudaMalloc allowed). Q,K stored transposed per batch: [b][d][s].
__device__ float g_qT[BATCH * DHEAD * SEQ];
__device__ float g_kT[BATCH * DHEAD * SEQ];
__device__ float g_v [ROWS_TOTAL * DHEAD];   // natural [token][d]

// ---------------------------------------------------------------------------
// Kernel 1: fused QKV projection (Q/K epilogue transposed).
// ---------------------------------------------------------------------------
__global__ __launch_bounds__(256) void proj_kernel(
    const float* __restrict__ x,
    const float* __restrict__ Wq, const float* __restrict__ bq,
    const float* __restrict__ Wk, const float* __restrict__ bk,
    const float* __restrict__ Wv, const float* __restrict__ bv)
{
    constexpr int BM = 64;
    constexpr int KC = 16;
    constexpr int NT = 192;

    __shared__ __align__(16) float xs[KC][68];
    __shared__ __align__(16) float ws[KC][NT];

    const int tid = threadIdx.x;
    const int ty  = tid >> 4;
    const int tx  = tid & 15;
    const int rowBase = blockIdx.x * BM;

    float acc[4][12];
#pragma unroll
    for (int i = 0; i < 4; i++)
#pragma unroll
        for (int j = 0; j < 12; j++) acc[i][j] = 0.f;

    for (int k0 = 0; k0 < HID; k0 += KC) {
        __syncthreads();
        {
            int row = tid >> 2;
            int cs  = (tid & 3) * 4;
            float4 xv = *(const float4*)(x + (size_t)(rowBase + row) * HID + k0 + cs);
            xs[cs + 0][row] = xv.x;
            xs[cs + 1][row] = xv.y;
            xs[cs + 2][row] = xv.z;
            xs[cs + 3][row] = xv.w;
        }
#pragma unroll
        for (int r = 0; r < 3; r++) {
            int p   = tid + 256 * r;
            int kk  = p / 48;
            int col = (p % 48) * 4;
            const float* src; int cc;
            if (col < 64)       { src = Wq; cc = col; }
            else if (col < 128) { src = Wk; cc = col - 64; }
            else                { src = Wv; cc = col - 128; }
            float4 wv = *(const float4*)(src + (size_t)(k0 + kk) * DHEAD + cc);
            *(float4*)&ws[kk][col] = wv;
        }
        __syncthreads();

#pragma unroll
        for (int kk = 0; kk < KC; kk++) {
            float4 a  = *(const float4*)&xs[kk][ty * 4];
            float4 b0 = *(const float4*)&ws[kk][tx * 12 + 0];
            float4 b1 = *(const float4*)&ws[kk][tx * 12 + 4];
            float4 b2 = *(const float4*)&ws[kk][tx * 12 + 8];
            float av[4]  = {a.x, a.y, a.z, a.w};
            float bv2[12] = {b0.x, b0.y, b0.z, b0.w,
                             b1.x, b1.y, b1.z, b1.w,
                             b2.x, b2.y, b2.z, b2.w};
#pragma unroll
            for (int i = 0; i < 4; i++)
#pragma unroll
                for (int j = 0; j < 12; j++)
                    acc[i][j] += av[i] * bv2[j];
        }
    }

    float bias[12];
#pragma unroll
    for (int j = 0; j < 12; j++) {
        int col = tx * 12 + j;
        if (col < 64)       bias[j] = bq[col];
        else if (col < 128) bias[j] = bk[col - 64];
        else                bias[j] = bv[col - 128];
    }
#pragma unroll
    for (int i = 0; i < 4; i++) {
        int row = rowBase + ty * 4 + i;       // global token index
        int b   = row >> 11;                  // /2048
        int s   = row & (SEQ - 1);
#pragma unroll
        for (int j = 0; j < 12; j++) {
            int col = tx * 12 + j;
            float val = acc[i][j] + bias[j];
            if (col < 64) {
                g_qT[(size_t)b * DHEAD * SEQ + (size_t)col * SEQ + s] = val;
            } else if (col < 128) {
                g_kT[(size_t)b * DHEAD * SEQ + (size_t)(col - 64) * SEQ + s] = val;
            } else {
                g_v[(size_t)row * DHEAD + (col - 128)] = val;
            }
        }
    }
}

// ---------------------------------------------------------------------------
// Kernel 2: flash attention, register-tiled.
//   Block = 128 threads, 64 queries. Grid = (32, 8) — 256 CTAs, 3/SM resident,
//   one wave on 148 SMs.
//   QK: micro-tile 4q x 4k (ty = tid>>3 query group, tx = tid&7 key group)
//   AV: micro-tile 4q x 8d (same ty; dg = tid&7 dim group)
//   cp.async double-buffered K/V/mask tiles.
// ---------------------------------------------------------------------------
struct AttnSmem {
    float Qs[DHEAD][QB];        // [d][q]   16 KB
    float Ks[2][DHEAD][TK];     // [buf][d][k]  16 KB
    float Vs[2][TK][DHEAD];     // [buf][k][d]  16 KB
    float Ps[TK][68];           // [k][q], padded rows
    int   msk[2][TK];
};

__device__ __forceinline__ void cp16(uint32_t dst, const void* src) {
    asm volatile("cp.async.cg.shared.global [%0], [%1], 16;\n"
                 :: "r"(dst), "l"(src));
}
__device__ __forceinline__ void cp_commit() {
    asm volatile("cp.async.commit_group;\n");
}
template<int N>
__device__ __forceinline__ void cp_wait() {
    asm volatile("cp.async.wait_group %0;\n" :: "n"(N));
}

__global__ __launch_bounds__(128) void attn_kernel(
    const int* __restrict__ mask, float* __restrict__ out)
{
    extern __shared__ __align__(16) char smem_raw[];
    AttnSmem& sm = *reinterpret_cast<AttnSmem*>(smem_raw);

    const int tid = threadIdx.x;
    const int ty  = tid >> 3;    // 0..15  query group (4 queries)
    const int tx  = tid & 7;     // 0..7   key group (4 keys) in QK phase
    const int dg  = tid & 7;     // 0..7   dim group (8 dims) in AV phase
    const int b   = blockIdx.y;
    const int qbase = blockIdx.x * QB;

    const float* Qg = g_qT + (size_t)b * DHEAD * SEQ;
    const float* Kg = g_kT + (size_t)b * DHEAD * SEQ;
    const float* Vg = g_v  + (size_t)b * SEQ * DHEAD;
    const int*   Mg = mask + (size_t)b * SEQ;

    // --- load Q tile [64d][64q] (one-time, plain loads) ---
#pragma unroll
    for (int r = 0; r < 8; r++) {
        int p = tid + 128 * r;              // 0..1023 float4 slots
        int d = p >> 4;
        int c = (p & 15) * 4;
        *(float4*)&sm.Qs[d][c] = *(const float4*)(Qg + (size_t)d * SEQ + qbase + c);
    }

    auto prefetch = [&](int t, int buf) {
        int kt = t * TK;
        // K: 64 rows x 8 float4
#pragma unroll
        for (int r = 0; r < 4; r++) {
            int p = tid + 128 * r;          // 0..511
            int d = p >> 3;
            int c = (p & 7) * 4;
            cp16((uint32_t)__cvta_generic_to_shared(&sm.Ks[buf][d][c]),
                 Kg + (size_t)d * SEQ + kt + c);
        }
        // V: 32 rows x 16 float4
#pragma unroll
        for (int r = 0; r < 4; r++) {
            int p = tid + 128 * r;          // 0..511
            int k = p >> 4;
            int c = (p & 15) * 4;
            cp16((uint32_t)__cvta_generic_to_shared(&sm.Vs[buf][k][c]),
                 Vg + (size_t)(kt + k) * DHEAD + c);
        }
        // mask: 32 ints = 8 x 16B
        if (tid < 8) {
            cp16((uint32_t)__cvta_generic_to_shared(&sm.msk[buf][tid * 4]),
                 Mg + kt + tid * 4);
        }
    };

    float o[4][8];
    float m[4], l[4];
#pragma unroll
    for (int i = 0; i < 4; i++) {
        m[i] = -1e30f; l[i] = 0.f;
#pragma unroll
        for (int d = 0; d < 8; d++) o[i][d] = 0.f;
    }

    prefetch(0, 0);
    cp_commit();

    for (int t = 0; t < NTILES; t++) {
        const int buf = t & 1;
        if (t + 1 < NTILES) {
            prefetch(t + 1, buf ^ 1);
            cp_commit();
            cp_wait<1>();
        } else {
            cp_wait<0>();
        }
        __syncthreads();

        // ---------- QK^T: acc[4q][4k] ----------
        float acc[4][4];
#pragma unroll
        for (int i = 0; i < 4; i++)
#pragma unroll
            for (int j = 0; j < 4; j++) acc[i][j] = 0.f;

#pragma unroll
        for (int d = 0; d < DHEAD; d++) {
            float4 qv = *(const float4*)&sm.Qs[d][ty * 4];
            float4 kv = *(const float4*)&sm.Ks[buf][d][tx * 4];
            float qa[4] = {qv.x, qv.y, qv.z, qv.w};
            float ka[4] = {kv.x, kv.y, kv.z, kv.w};
#pragma unroll
            for (int i = 0; i < 4; i++)
#pragma unroll
                for (int j = 0; j < 4; j++)
                    acc[i][j] += qa[i] * ka[j];
        }

        // mask + scale -> scores
        int mk[4];
#pragma unroll
        for (int j = 0; j < 4; j++) mk[j] = sm.msk[buf][tx * 4 + j];
#pragma unroll
        for (int i = 0; i < 4; i++)
#pragma unroll
            for (int j = 0; j < 4; j++)
                acc[i][j] = mk[j] ? acc[i][j] * 0.125f : -1e30f;

        // ---------- online softmax ----------
        float alpha[4], mnew[4];
#pragma unroll
        for (int i = 0; i < 4; i++) {
            float tmax = fmaxf(fmaxf(acc[i][0], acc[i][1]),
                               fmaxf(acc[i][2], acc[i][3]));
            tmax = fmaxf(tmax, __shfl_xor_sync(0xffffffffu, tmax, 1));
            tmax = fmaxf(tmax, __shfl_xor_sync(0xffffffffu, tmax, 2));
            tmax = fmaxf(tmax, __shfl_xor_sync(0xffffffffu, tmax, 4));
            mnew[i] = fmaxf(m[i], tmax);
            alpha[i] = __expf(m[i] - mnew[i]);
            m[i] = mnew[i];
        }

        float psum[4];
#pragma unroll
        for (int i = 0; i < 4; i++) {
            float p0 = __expf(acc[i][0] - mnew[i]);
            float p1 = __expf(acc[i][1] - mnew[i]);
            float p2 = __expf(acc[i][2] - mnew[i]);
            float p3 = __expf(acc[i][3] - mnew[i]);
            acc[i][0] = p0; acc[i][1] = p1; acc[i][2] = p2; acc[i][3] = p3;
            psum[i] = (p0 + p1) + (p2 + p3);
            psum[i] += __shfl_xor_sync(0xffffffffu, psum[i], 1);
            psum[i] += __shfl_xor_sync(0xffffffffu, psum[i], 2);
            psum[i] += __shfl_xor_sync(0xffffffffu, psum[i], 4);
            l[i] = l[i] * alpha[i] + psum[i];
        }

        // write P -> smem [k][q]
#pragma unroll
        for (int j = 0; j < 4; j++)
#pragma unroll
            for (int i = 0; i < 4; i++)
                sm.Ps[tx * 4 + j][ty * 4 + i] = acc[i][j];

        // rescale o
#pragma unroll
        for (int i = 0; i < 4; i++)
#pragma unroll
            for (int d = 0; d < 8; d++) o[i][d] *= alpha[i];

        __syncthreads();

        // ---------- AV: o[4q][8d] += P[4q][32k] * V[32k][8d] ----------
#pragma unroll
        for (int k = 0; k < TK; k++) {
            float4 pv = *(const float4*)&sm.Ps[k][ty * 4];
            float4 v0 = *(const float4*)&sm.Vs[buf][k][dg * 8];
            float4 v1 = *(const float4*)&sm.Vs[buf][k][dg * 8 + 4];
            float pa[4] = {pv.x, pv.y, pv.z, pv.w};
            float va[8] = {v0.x, v0.y, v0.z, v0.w, v1.x, v1.y, v1.z, v1.w};
#pragma unroll
            for (int i = 0; i < 4; i++)
#pragma unroll
                for (int d = 0; d < 8; d++)
                    o[i][d] += pa[i] * va[d];
        }

        __syncthreads();
    }

    // ---------- epilogue ----------
#pragma unroll
    for (int i = 0; i < 4; i++) {
        float inv = 1.f / l[i];
        int q = qbase + ty * 4 + i;
        float* dst = out + ((size_t)b * SEQ + q) * DHEAD + dg * 8;
        float4 r0, r1;
        r0.x = o[i][0] * inv; r0.y = o[i][1] * inv;
        r0.z = o[i][2] * inv; r0.w = o[i][3] * inv;
        r1.x = o[i][4] * inv; r1.y = o[i][5] * inv;
        r1.z = o[i][6] * inv; r1.w = o[i][7] * inv;
        *(float4*)(dst)     = r0;
        *(float4*)(dst + 4) = r1;
    }
}

// ---------------------------------------------------------------------------
extern "C" void kernel_launch(void* const* d_in, const int* in_sizes, int n_in,
                              void* d_out, int out_size)
{
    const float* x    = (const float*)d_in[0];
    const int*   mask = (const int*)  d_in[1];
    const float* Wq   = (const float*)d_in[2];
    const float* bq   = (const float*)d_in[3];
    const float* Wk   = (const float*)d_in[4];
    const float* bk   = (const float*)d_in[5];
    const float* Wv   = (const float*)d_in[6];
    const float* bv   = (const float*)d_in[7];
    float* out = (float*)d_out;

    static_assert(sizeof(AttnSmem) < 160 * 1024, "smem");
    cudaFuncSetAttribute(attn_kernel,
                         cudaFuncAttributeMaxDynamicSharedMemorySize,
                         (int)sizeof(AttnSmem));

    proj_kernel<<<ROWS_TOTAL / 64, 256>>>(x, Wq, bq, Wk, bk, Wv, bv);
    attn_kernel<<<dim3(SEQ / QB, BATCH), 128, sizeof(AttnSmem)>>>(mask, out);
}